// round 2
// baseline (speedup 1.0000x reference)
#include <cuda_runtime.h>

// Problem constants (fixed by dataset: B=16, H=1024, W=2048, G=8, C=19)
#define NB      524288          // number of 8x8 label blocks = 16*128*256
#define NC      19
#define WID     2048
#define HEI     1024
#define GS      8
#define WB      (WID/GS)        // 256 blocks along W
#define HB      (HEI/GS)        // 128 blocks along H
#define NELEM   (NB*NC)         // 9961472 (pred elements)
#define NTHB    (NELEM/4)       // 2490368 float4 threads
#define CTAS_B  (NTHB/256)      // 9728 CTAs (exact)

// Allocation-free scratch (__device__ globals per harness rules)
__device__ unsigned int g_masks[NB + 4];
__device__ double       g_partials[CTAS_B];

// ---------------------------------------------------------------------------
// Kernel 1: per-block 19-bit presence mask from targets.
// One thread per 8x8 block: 16x LDG.128 (int4), 64x (shift|or).
// Consecutive threads -> consecutive 32B chunks along W: coalesced, all bytes used.
// ---------------------------------------------------------------------------
__global__ void __launch_bounds__(256) mask_kernel(const int* __restrict__ tgt)
{
    unsigned int t  = blockIdx.x * 256u + threadIdx.x;
    unsigned int bw = t & (WB - 1);          // 0..255
    unsigned int bh = (t >> 8) & (HB - 1);   // 0..127
    unsigned int b  = t >> 15;               // 0..15

    size_t base = ((size_t)(b * HEI + bh * GS)) * WID + (size_t)bw * GS;
    const int4* p = (const int4*)(tgt + base);   // 16B-aligned: base multiple of 8 ints

    unsigned int m = 0u;
#pragma unroll
    for (int r = 0; r < 8; r++) {
        int4 v0 = p[r * (WID / 4)];
        int4 v1 = p[r * (WID / 4) + 1];
        m |= (1u << v0.x) | (1u << v0.y) | (1u << v0.z) | (1u << v0.w);
        m |= (1u << v1.x) | (1u << v1.y) | (1u << v1.z) | (1u << v1.w);
    }
    g_masks[t] = m;
}

// Numerically stable softplus: max(x,0) + log(1 + exp(-|x|))
__device__ __forceinline__ float softplus_f(float x)
{
    float e = __expf(-fabsf(x));
    return fmaxf(x, 0.0f) + __logf(1.0f + e);
}

// ---------------------------------------------------------------------------
// Kernel 2: loss over flat preds array, one float4 per thread (coalesced).
// loss(x, t) = softplus(x) - t*x  (t = presence bit)
// Deterministic reduction: warp shuffle -> smem -> per-CTA double partial.
// ---------------------------------------------------------------------------
__global__ void __launch_bounds__(256) loss_kernel(const float* __restrict__ preds)
{
    unsigned int j  = blockIdx.x * 256u + threadIdx.x;     // < NTHB
    unsigned int e0 = j * 4u;                              // flat element index
    unsigned int q  = e0 / 19u;                            // block index (magic div)
    unsigned int c0 = e0 - q * 19u;                        // class of first element

    float4 x = ((const float4*)preds)[j];
    unsigned int m0 = g_masks[q];
    unsigned int m1 = g_masks[q + 1];                      // safe: padded array

    float xs0 = x.x, xs1 = x.y, xs2 = x.z, xs3 = x.w;
    float s = 0.0f;
#pragma unroll
    for (int k = 0; k < 4; k++) {
        float xv = (k == 0) ? xs0 : (k == 1) ? xs1 : (k == 2) ? xs2 : xs3;
        unsigned int c  = c0 + (unsigned int)k;
        unsigned int mm = m0;
        if (c >= 19u) { c -= 19u; mm = m1; }
        float sp = softplus_f(xv);
        s += ((mm >> c) & 1u) ? (sp - xv) : sp;
    }

    // warp reduce
#pragma unroll
    for (int o = 16; o > 0; o >>= 1)
        s += __shfl_xor_sync(0xffffffffu, s, o);

    __shared__ float ws[8];
    if ((threadIdx.x & 31u) == 0u) ws[threadIdx.x >> 5] = s;
    __syncthreads();
    if (threadIdx.x < 32u) {
        float v = (threadIdx.x < 8u) ? ws[threadIdx.x] : 0.0f;
#pragma unroll
        for (int o = 4; o > 0; o >>= 1)
            v += __shfl_xor_sync(0xffffffffu, v, o);
        if (threadIdx.x == 0u)
            g_partials[blockIdx.x] = (double)v;
    }
}

// ---------------------------------------------------------------------------
// Kernel 3: deterministic final reduction of per-CTA partials -> mean -> d_out
// ---------------------------------------------------------------------------
__global__ void __launch_bounds__(256) final_kernel(float* __restrict__ out)
{
    double s = 0.0;
    for (unsigned int i = threadIdx.x; i < (unsigned int)CTAS_B; i += 256u)
        s += g_partials[i];

    __shared__ double sh[256];
    sh[threadIdx.x] = s;
    __syncthreads();
#pragma unroll
    for (int o = 128; o > 0; o >>= 1) {
        if (threadIdx.x < (unsigned int)o) sh[threadIdx.x] += sh[threadIdx.x + o];
        __syncthreads();
    }
    if (threadIdx.x == 0)
        out[0] = (float)(sh[0] / ((double)NB * (double)NC));
}

// ---------------------------------------------------------------------------
extern "C" void kernel_launch(void* const* d_in, const int* in_sizes, int n_in,
                              void* d_out, int out_size)
{
    const float* preds = (const float*)d_in[0];
    const int*   tgt   = (const int*)d_in[1];
    // d_in[2] = grid_size (always 8 for this problem's shapes)

    mask_kernel<<<NB / 256, 256>>>(tgt);
    loss_kernel<<<CTAS_B, 256>>>(preds);
    final_kernel<<<1, 256>>>((float*)d_out);
}

// round 3
// speedup vs baseline: 1.0140x; 1.0140x over previous
#include <cuda_runtime.h>

// Problem constants (fixed by dataset: B=16, H=1024, W=2048, G=8, C=19)
#define NB      524288          // number of 8x8 label blocks = 16*128*256
#define NC      19
#define WID     2048
#define HEI     1024
#define GS      8
#define WB      (WID/GS)        // 256 blocks along W
#define HB      (HEI/GS)        // 128 blocks along H
#define NELEM   (NB*NC)         // 9961472 (pred elements)
#define NTHB    (NELEM/4)       // 2490368 float4 threads
#define CTAS_B  (NTHB/256)      // 9728 CTAs (exact)

// Allocation-free scratch (__device__ globals per harness rules)
__device__ unsigned int g_masks[NB + 4];
__device__ double       g_partials[CTAS_B];

// ---------------------------------------------------------------------------
// Kernel 1: per-block 19-bit presence mask from targets.
// One thread per 8x8 block: 16x LDG.128 (int4), 64x (shift|or).
// Consecutive threads -> consecutive 32B chunks along W: coalesced, all bytes used.
// ---------------------------------------------------------------------------
__global__ void __launch_bounds__(256) mask_kernel(const int* __restrict__ tgt)
{
    unsigned int t  = blockIdx.x * 256u + threadIdx.x;
    unsigned int bw = t & (WB - 1);          // 0..255
    unsigned int bh = (t >> 8) & (HB - 1);   // 0..127
    unsigned int b  = t >> 15;               // 0..15

    size_t base = ((size_t)(b * HEI + bh * GS)) * WID + (size_t)bw * GS;
    const int4* p = (const int4*)(tgt + base);   // 16B-aligned: base multiple of 8 ints

    unsigned int m = 0u;
#pragma unroll
    for (int r = 0; r < 8; r++) {
        int4 v0 = p[r * (WID / 4)];
        int4 v1 = p[r * (WID / 4) + 1];
        m |= (1u << v0.x) | (1u << v0.y) | (1u << v0.z) | (1u << v0.w);
        m |= (1u << v1.x) | (1u << v1.y) | (1u << v1.z) | (1u << v1.w);
    }
    g_masks[t] = m;
}

// Numerically stable softplus: max(x,0) + log(1 + exp(-|x|))
__device__ __forceinline__ float softplus_f(float x)
{
    float e = __expf(-fabsf(x));
    return fmaxf(x, 0.0f) + __logf(1.0f + e);
}

// ---------------------------------------------------------------------------
// Kernel 2: loss over flat preds array, one float4 per thread (coalesced).
// loss(x, t) = softplus(x) - t*x  (t = presence bit)
// Deterministic reduction: warp shuffle -> smem -> per-CTA double partial.
// ---------------------------------------------------------------------------
__global__ void __launch_bounds__(256) loss_kernel(const float* __restrict__ preds)
{
    unsigned int j  = blockIdx.x * 256u + threadIdx.x;     // < NTHB
    unsigned int e0 = j * 4u;                              // flat element index
    unsigned int q  = e0 / 19u;                            // block index (magic div)
    unsigned int c0 = e0 - q * 19u;                        // class of first element

    float4 x = ((const float4*)preds)[j];
    unsigned int m0 = g_masks[q];
    unsigned int m1 = g_masks[q + 1];                      // safe: padded array

    float xs0 = x.x, xs1 = x.y, xs2 = x.z, xs3 = x.w;
    float s = 0.0f;
#pragma unroll
    for (int k = 0; k < 4; k++) {
        float xv = (k == 0) ? xs0 : (k == 1) ? xs1 : (k == 2) ? xs2 : xs3;
        unsigned int c  = c0 + (unsigned int)k;
        unsigned int mm = m0;
        if (c >= 19u) { c -= 19u; mm = m1; }
        float sp = softplus_f(xv);
        s += ((mm >> c) & 1u) ? (sp - xv) : sp;
    }

    // warp reduce
#pragma unroll
    for (int o = 16; o > 0; o >>= 1)
        s += __shfl_xor_sync(0xffffffffu, s, o);

    __shared__ float ws[8];
    if ((threadIdx.x & 31u) == 0u) ws[threadIdx.x >> 5] = s;
    __syncthreads();
    if (threadIdx.x < 32u) {
        float v = (threadIdx.x < 8u) ? ws[threadIdx.x] : 0.0f;
#pragma unroll
        for (int o = 4; o > 0; o >>= 1)
            v += __shfl_xor_sync(0xffffffffu, v, o);
        if (threadIdx.x == 0u)
            g_partials[blockIdx.x] = (double)v;
    }
}

// ---------------------------------------------------------------------------
// Kernel 3: deterministic final reduction of per-CTA partials -> mean -> d_out
// ---------------------------------------------------------------------------
__global__ void __launch_bounds__(256) final_kernel(float* __restrict__ out)
{
    double s = 0.0;
    for (unsigned int i = threadIdx.x; i < (unsigned int)CTAS_B; i += 256u)
        s += g_partials[i];

    __shared__ double sh[256];
    sh[threadIdx.x] = s;
    __syncthreads();
#pragma unroll
    for (int o = 128; o > 0; o >>= 1) {
        if (threadIdx.x < (unsigned int)o) sh[threadIdx.x] += sh[threadIdx.x + o];
        __syncthreads();
    }
    if (threadIdx.x == 0)
        out[0] = (float)(sh[0] / ((double)NB * (double)NC));
}

// ---------------------------------------------------------------------------
extern "C" void kernel_launch(void* const* d_in, const int* in_sizes, int n_in,
                              void* d_out, int out_size)
{
    const float* preds = (const float*)d_in[0];
    const int*   tgt   = (const int*)d_in[1];
    // d_in[2] = grid_size (always 8 for this problem's shapes)

    mask_kernel<<<NB / 256, 256>>>(tgt);
    loss_kernel<<<CTAS_B, 256>>>(preds);
    final_kernel<<<1, 256>>>((float*)d_out);
}

// round 4
// speedup vs baseline: 1.1815x; 1.1652x over previous
#include <cuda_runtime.h>

// Problem constants (fixed by dataset: B=16, H=1024, W=2048, G=8, C=19)
#define NB      524288          // number of 8x8 label blocks = 16*128*256
#define NC      19
#define WID     2048
#define HEI     1024
#define GS      8
#define WB      (WID/GS)        // 256 blocks along W
#define HB      (HEI/GS)        // 128 blocks along H
#define NELEM   (NB*NC)         // 9961472 pred elements
#define BLOCKS_PER_CTA 256      // one row of label blocks per CTA
#define NCTAS   (NB/BLOCKS_PER_CTA)            // 2048
#define F_PER_CTA (BLOCKS_PER_CTA*NC)          // 4864 floats (multiple of 4)
#define V_PER_CTA (F_PER_CTA/4)                // 1216 float4

// Allocation-free scratch (__device__ globals per harness rules)
__device__ double       g_partials[NCTAS];
__device__ unsigned int g_count = 0;           // self-resetting completion counter

// Numerically stable softplus: max(x,0) + log(1 + exp(-|x|))
__device__ __forceinline__ float softplus_f(float x)
{
    float e = __expf(-fabsf(x));
    return fmaxf(x, 0.0f) + __logf(1.0f + e);
}

// ---------------------------------------------------------------------------
// Fused kernel: per-CTA (mask build -> loss -> partial), last CTA finalizes.
// ---------------------------------------------------------------------------
__global__ void __launch_bounds__(256) fused_kernel(const int*   __restrict__ tgt,
                                                    const float* __restrict__ preds,
                                                    float*       __restrict__ out)
{
    __shared__ unsigned int sm_mask[BLOCKS_PER_CTA + 1];
    __shared__ float  ws[8];
    __shared__ double sh[256];

    const unsigned int tid = threadIdx.x;
    const unsigned int cta = blockIdx.x;

    // ---- Phase A: build 256 presence masks for this row of blocks ----
    // Global block id t = cta*256 + tid; bw = tid (full W row per CTA).
    {
        unsigned int bh = cta & (HB - 1);        // 0..127
        unsigned int b  = cta >> 7;              // 0..15
        size_t base = ((size_t)(b * HEI + bh * GS)) * WID + (size_t)tid * GS;
        const int4* p = (const int4*)(tgt + base);   // 16B aligned

        unsigned int m = 0u;
#pragma unroll
        for (int r = 0; r < 8; r++) {
            int4 v0 = p[r * (WID / 4)];
            int4 v1 = p[r * (WID / 4) + 1];
            m |= (1u << v0.x) | (1u << v0.y) | (1u << v0.z) | (1u << v0.w);
            m |= (1u << v1.x) | (1u << v1.y) | (1u << v1.z) | (1u << v1.w);
        }
        sm_mask[tid] = m;
        if (tid == 0) sm_mask[BLOCKS_PER_CTA] = 0u;   // pad (never addressed w/ valid c)
    }
    __syncthreads();

    // ---- Phase B: stream this CTA's contiguous preds slice (coalesced f4) ----
    const float4* pv = (const float4*)(preds + (size_t)cta * F_PER_CTA);
    float s = 0.0f;
#pragma unroll
    for (int it = 0; it < 5; it++) {
        unsigned int j = tid + (unsigned int)it * 256u;
        if (j < V_PER_CTA) {
            unsigned int e0 = j * 4u;                  // local flat element index
            unsigned int q  = e0 / 19u;                // local block (magic div)
            unsigned int c0 = e0 - q * 19u;
            // 64-bit concatenated mask: bits [0,19) = block q, [19,38) = block q+1
            unsigned long long mm = (unsigned long long)sm_mask[q]
                                  | ((unsigned long long)sm_mask[q + 1] << 19);
            float4 x = pv[j];
            float sp0 = softplus_f(x.x), sp1 = softplus_f(x.y);
            float sp2 = softplus_f(x.z), sp3 = softplus_f(x.w);
            s += ((mm >> (c0 + 0)) & 1ull) ? (sp0 - x.x) : sp0;
            s += ((mm >> (c0 + 1)) & 1ull) ? (sp1 - x.y) : sp1;
            s += ((mm >> (c0 + 2)) & 1ull) ? (sp2 - x.z) : sp2;
            s += ((mm >> (c0 + 3)) & 1ull) ? (sp3 - x.w) : sp3;
        }
    }

    // ---- CTA reduction -> double partial ----
#pragma unroll
    for (int o = 16; o > 0; o >>= 1)
        s += __shfl_xor_sync(0xffffffffu, s, o);
    if ((tid & 31u) == 0u) ws[tid >> 5] = s;
    __syncthreads();
    bool is_last = false;
    if (tid < 32u) {
        float v = (tid < 8u) ? ws[tid] : 0.0f;
#pragma unroll
        for (int o = 4; o > 0; o >>= 1)
            v += __shfl_xor_sync(0xffffffffu, v, o);
        if (tid == 0u) {
            g_partials[cta] = (double)v;
            __threadfence();
            unsigned int done = atomicAdd(&g_count, 1u);
            is_last = (done == (unsigned int)(NCTAS - 1));
            ws[0] = is_last ? 1.0f : 0.0f;   // broadcast via smem
        }
    }
    __syncthreads();
    if (ws[0] == 0.0f) return;

    // ---- Last CTA: deterministic final reduction over all partials ----
    double d = 0.0;
    for (unsigned int i = tid; i < (unsigned int)NCTAS; i += 256u)
        d += g_partials[i];
    sh[tid] = d;
    __syncthreads();
#pragma unroll
    for (int o = 128; o > 0; o >>= 1) {
        if (tid < (unsigned int)o) sh[tid] += sh[tid + o];
        __syncthreads();
    }
    if (tid == 0) {
        out[0] = (float)(sh[0] / ((double)NB * (double)NC));
        g_count = 0;                         // reset for next graph replay
    }
}

// ---------------------------------------------------------------------------
extern "C" void kernel_launch(void* const* d_in, const int* in_sizes, int n_in,
                              void* d_out, int out_size)
{
    const float* preds = (const float*)d_in[0];
    const int*   tgt   = (const int*)d_in[1];
    // d_in[2] = grid_size (always 8 for this problem's shapes)

    fused_kernel<<<NCTAS, 256>>>(tgt, preds, (float*)d_out);
}